// round 10
// baseline (speedup 1.0000x reference)
#include <cuda_runtime.h>
#include <utility>

#define RB 20
#define RA 19
#define MUL 128
#define NC 128
#define NBATCH 1024
#define D1 9
#define DZ 25
#define ZSTRIDE 28     // padded z row stride (112B, 16B aligned)
#define ZROW (NC * ZSTRIDE)          // 3584 floats per node in scratch
#define XYSTRIDE 20    // [xd1..8][yd1..8][xd0][yd0][pad2] (80B, 16B aligned)
#define RSTRIDE 19     // reduction row stride (odd -> conflict-free)

// ===================== compile-time selection rules =====================
__host__ __device__ constexpr int lof(int d) {
    return (d < 1) ? 0 : (d < 4) ? 1 : (d < 9) ? 2 : (d < 16) ? 3 : 4;
}
__host__ __device__ constexpr bool gaunt_nz(int i, int j, int d) {
    const int l1 = lof(i), m1 = i - l1 * l1 - l1;
    const int l2 = lof(j), m2 = j - l2 * l2 - l2;
    const int L  = lof(d), M  = d - L * L - L;
    if ((l1 + l2 + L) & 1) return false;
    const int lo = (l1 > l2) ? (l1 - l2) : (l2 - l1);
    if (L < lo || L > l1 + l2) return false;
    const int f1 = m1 < 0 ? -m1 : m1;
    const int f2 = m2 < 0 ? -m2 : m2;
    const int F  = M  < 0 ? -M  : M;
    const int fd = (f1 > f2) ? (f1 - f2) : (f2 - f1);
    if (!(F == f1 + f2 || F == fd)) return false;
    if (((m1 < 0) + (m2 < 0) + (M < 0)) & 1) return false;
    return true;
}

// ===================== compile-time Gaunt table =====================
namespace cgaunt {

constexpr double PI = 3.14159265358979323846;

constexpr double csqrt(double x) {
    double r = (x > 1.0) ? x : 1.0;
    for (int i = 0; i < 80; ++i) r = 0.5 * (r + x / r);
    return r;
}
constexpr double redang(double x) {
    while (x >  PI) x -= 2.0 * PI;
    while (x < -PI) x += 2.0 * PI;
    return x;
}
constexpr double ccos(double x) {
    x = redang(x);
    double x2 = x * x, t = 1.0, s = 1.0;
    for (int k = 1; k <= 22; ++k) { t *= -x2 / ((2.0 * k - 1.0) * (2.0 * k)); s += t; }
    return s;
}
constexpr double csin(double x) {
    x = redang(x);
    double x2 = x * x, t = x, s = x;
    for (int k = 1; k <= 22; ++k) { t *= -x2 / ((2.0 * k) * (2.0 * k + 1.0)); s += t; }
    return s;
}
constexpr double cfact(int k) { double f = 1.0; for (int v = 2; v <= k; ++v) f *= v; return f; }

constexpr double alegP(int l, int m, double x) {
    double pmm = 1.0;
    if (m > 0) {
        double df = 1.0;
        for (int k = 1; k < 2 * m; k += 2) df *= (double)k;
        double somx2 = csqrt(1.0 - x * x);
        double s = 1.0;
        for (int k = 0; k < m; ++k) s *= somx2;
        pmm = ((m & 1) ? -1.0 : 1.0) * df * s;
    }
    if (l == m) return pmm;
    double pmmp1 = x * (2.0 * m + 1.0) * pmm;
    if (l == m + 1) return pmmp1;
    for (int ll = m + 2; ll <= l; ++ll) {
        double p = ((2.0 * ll - 1.0) * x * pmmp1 - (ll + m - 1.0) * pmm) / (double)(ll - m);
        pmm = pmmp1; pmmp1 = p;
    }
    return pmmp1;
}

struct GTab { double g[81][DZ]; };

constexpr GTab make_gaunt() {
    GTab T{};
    double ct[RB] = {}, qw[RB] = {};
    for (int i = 0; i < RB; ++i) {
        double xv = ccos(PI * (i + 0.75) / (RB + 0.5));
        double dp = 0.0;
        for (int it = 0; it < 60; ++it) {
            double p0 = 1.0, p1 = xv;
            for (int k = 2; k <= RB; ++k) {
                double p = ((2.0 * k - 1.0) * xv * p1 - (k - 1.0) * p0) / (double)k;
                p0 = p1; p1 = p;
            }
            dp = RB * (xv * p1 - p0) / (xv * xv - 1.0);
            xv -= p1 / dp;
        }
        {
            double p0 = 1.0, p1 = xv;
            for (int k = 2; k <= RB; ++k) {
                double p = ((2.0 * k - 1.0) * xv * p1 - (k - 1.0) * p0) / (double)k;
                p0 = p1; p1 = p;
            }
            dp = RB * (xv * p1 - p0) / (xv * xv - 1.0);
        }
        ct[i] = xv;
        qw[i] = 2.0 / ((1.0 - xv * xv) * dp * dp);
    }
    double Pn[DZ][RB] = {}, U[DZ][RA] = {};
    for (int d = 0; d < DZ; ++d) {
        int l = lof(d);
        int m = d - l * l - l;
        int am = m < 0 ? -m : m;
        double nlm = csqrt((2.0 * l + 1.0) / (4.0 * PI) * cfact(l - am) / cfact(l + am));
        for (int b = 0; b < RB; ++b) Pn[d][b] = nlm * alegP(l, am, ct[b]);
        for (int a = 0; a < RA; ++a) {
            double al = 2.0 * PI * (double)a / (double)RA;
            U[d][a] = (m == 0) ? 1.0
                    : (m > 0 ? csqrt(2.0) * ccos((double)m * al)
                             : csqrt(2.0) * csin((double)am * al));
        }
    }
    const double scale = (2.0 * PI / (double)RA) / (double)MUL / csqrt((double)NC);
    for (int i = 0; i < 9; ++i)
        for (int j = 0; j < 9; ++j)
            for (int d = 0; d < DZ; ++d) {
                if (!gaunt_nz(i, j, d)) { T.g[i * 9 + j][d] = 0.0; continue; }
                double angs = 0.0;
                for (int a = 0; a < RA; ++a) angs += U[i][a] * U[j][a] * U[d][a];
                double bets = 0.0;
                for (int b = 0; b < RB; ++b) bets += qw[b] * Pn[i][b] * Pn[j][b] * Pn[d][b];
                T.g[i * 9 + j][d] = angs * bets * scale;
            }
    return T;
}

constexpr GTab GG = make_gaunt();

} // namespace cgaunt

// ===================== static_for =====================
template <typename F, int... Is>
__device__ __forceinline__ void sfor_impl(F&& f, std::integer_sequence<int, Is...>) {
    (f(std::integral_constant<int, Is>{}), ...);
}
template <int N, typename F>
__device__ __forceinline__ void sfor(F&& f) {
    sfor_impl(static_cast<F&&>(f), std::make_integer_sequence<int, N>{});
}

// ===================== packed f32x2 helpers =====================
__device__ __forceinline__ unsigned long long pk2(float lo, float hi) {
    unsigned long long r;
    asm("mov.b64 %0, {%1, %2};" : "=l"(r) : "f"(lo), "f"(hi));
    return r;
}
__device__ __forceinline__ void ffma2(unsigned long long& d,
                                      unsigned long long a, unsigned long long b) {
    asm("fma.rn.f32x2 %0, %1, %2, %0;" : "+l"(d) : "l"(a), "l"(b));
}
__device__ __forceinline__ void unpk2(unsigned long long v, float& lo, float& hi) {
    asm("mov.b64 {%0, %1}, %2;" : "=f"(lo), "=f"(hi) : "l"(v));
}

// ===================== device scratch =====================
__device__ float4 WA[MUL * NC];    // (wx_l0, wx_l1, wx_l2, wy_l0) at [m*128+c]
__device__ float2 WB[MUL * NC];    // (wy_l1, wy_l2)
__device__ float4 WZ4[NC * NC];    // (wz_l0..wz_l3) at [cc*128+c]
__device__ float  WZ1[NC * NC];    // wz_l4
__device__ float  ZS[NBATCH * ZROW];   // 14.7 MB z scratch (padded rows)

__global__ void pack_weights(const float* __restrict__ wx,
                             const float* __restrict__ wy,
                             const float* __restrict__ wz) {
    int idx = blockIdx.x * 256 + threadIdx.x;   // 0..16383
    WA[idx] = make_float4(wx[idx], wx[16384 + idx], wx[32768 + idx], wy[idx]);
    WB[idx] = make_float2(wy[16384 + idx], wy[32768 + idx]);
    WZ4[idx] = make_float4(wz[idx], wz[16384 + idx], wz[32768 + idx], wz[49152 + idx]);
    WZ1[idx] = wz[65536 + idx];
}

// ======== sparse Gaunt contraction over an output d-range (CT coeffs) ========
template <int D0, int D1R>
__device__ __forceinline__ void gaunt_contract_range(const float* __restrict__ xc,
                                                     const float* __restrict__ yc,
                                                     float* __restrict__ z) {
    #pragma unroll
    for (int d = 0; d < D1R - D0; ++d) z[d] = 0.0f;
    sfor<9>([&](auto I) {
        constexpr int i = decltype(I)::value;
        sfor<9>([&](auto J) {
            constexpr int j = decltype(J)::value;
            float p = xc[i] * yc[j];
            sfor<D1R - D0>([&](auto Dd) {
                constexpr int d = D0 + decltype(Dd)::value;
                if constexpr (gaunt_nz(i, j, d)) {
                    constexpr float gv = (float)cgaunt::GG.g[i * 9 + j][d];
                    z[decltype(Dd)::value] = fmaf(p, gv, z[decltype(Dd)::value]);
                }
            });
        });
    });
}

// ===================== K1: linear-in + Gaunt -> z scratch =====================
// 256 threads: c = tid&127, h = tid>>7. Half h sums m in [h*64, h*64+64).
__global__ void __launch_bounds__(256, 4)
k1_linear_gaunt(const float* __restrict__ x, const float* __restrict__ y) {
    __shared__ __align__(16) float pool[ZROW];          // 14336 B: xy rows, then z rows
    __shared__ float red[NC * RSTRIDE];                 // 9728 B reduction buffer

    const int tid = threadIdx.x;
    const int c = tid & 127;
    const int h = tid >> 7;
    const int n = blockIdx.x;

    // ---- stage-in: xy row m = [xd1..8][yd1..8][xd0][yd0][pad2] ----
    {
        const float* xg = x + (size_t)n * MUL * D1;
        const float* yg = y + (size_t)n * MUL * D1;
        #pragma unroll
        for (int it = 0; it < 5; ++it) {
            int idx = tid + it * 256;
            if (idx < MUL * D1) {
                int m = idx / 9, dd = idx - m * 9;
                int kx = (dd == 0) ? 16 : (dd - 1);
                int ky = (dd == 0) ? 17 : (7 + dd);
                pool[m * XYSTRIDE + kx] = xg[idx];
                pool[m * XYSTRIDE + ky] = yg[idx];
            }
        }
    }
    __syncthreads();

    // ---- stage 1 partial: m in [h*64, h*64+64) ----
    unsigned long long Ax[4], Ay[4];
    float sx = 0.0f, sy = 0.0f;
    #pragma unroll
    for (int k = 0; k < 4; ++k) { Ax[k] = Ay[k] = 0ULL; }

    const int m0 = h * 64;
    #pragma unroll 4
    for (int mi = 0; mi < 64; ++mi) {
        const int m = m0 + mi;
        float4 wa = WA[m * NC + c];
        float2 wb = WB[m * NC + c];
        const float* row = &pool[m * XYSTRIDE];
        float4 xv0 = *(const float4*)(row);
        float4 xv1 = *(const float4*)(row + 4);
        float4 yv0 = *(const float4*)(row + 8);
        float4 yv1 = *(const float4*)(row + 12);
        float2 d0  = *(const float2*)(row + 16);
        ffma2(Ax[0], pk2(xv0.x, xv0.y), pk2(wa.y, wa.y));
        ffma2(Ax[1], pk2(xv0.z, xv0.w), pk2(wa.y, wa.z));
        ffma2(Ax[2], pk2(xv1.x, xv1.y), pk2(wa.z, wa.z));
        ffma2(Ax[3], pk2(xv1.z, xv1.w), pk2(wa.z, wa.z));
        sx += d0.x * wa.x;
        ffma2(Ay[0], pk2(yv0.x, yv0.y), pk2(wb.x, wb.x));
        ffma2(Ay[1], pk2(yv0.z, yv0.w), pk2(wb.x, wb.y));
        ffma2(Ay[2], pk2(yv1.x, yv1.y), pk2(wb.y, wb.y));
        ffma2(Ay[3], pk2(yv1.z, yv1.w), pk2(wb.y, wb.y));
        sy += d0.y * wa.w;
    }

    float xc[9], yc[9];
    xc[0] = sx; yc[0] = sy;
    #pragma unroll
    for (int k = 0; k < 4; ++k) {
        unpk2(Ax[k], xc[2 * k + 1], xc[2 * k + 2]);
        unpk2(Ay[k], yc[2 * k + 1], yc[2 * k + 2]);
    }

    // ---- cross-half reduction via red (stride 19, conflict-free) ----
    if (h == 1) {
        float* r = &red[c * RSTRIDE];
        #pragma unroll
        for (int k = 0; k < 9; ++k) { r[k] = xc[k]; r[9 + k] = yc[k]; }
    }
    __syncthreads();
    if (h == 0) {
        float* r = &red[c * RSTRIDE];
        #pragma unroll
        for (int k = 0; k < 9; ++k) { xc[k] += r[k]; yc[k] += r[9 + k]; }
        #pragma unroll
        for (int k = 0; k < 9; ++k) { r[k] = xc[k]; r[9 + k] = yc[k]; }
    }
    __syncthreads();
    if (h == 1) {
        const float* r = &red[c * RSTRIDE];
        #pragma unroll
        for (int k = 0; k < 9; ++k) { xc[k] = r[k]; yc[k] = r[9 + k]; }
    }

    // ---- Gaunt: each half computes its d-range, writes its z slice ----
    // (pool xy reads all completed before first sync above)
    if (h == 0) {
        float zh[13];
        gaunt_contract_range<0, 13>(xc, yc, zh);
        float* zr = &pool[c * ZSTRIDE];
        *(float4*)(zr)     = make_float4(zh[0], zh[1], zh[2],  zh[3]);
        *(float4*)(zr + 4) = make_float4(zh[4], zh[5], zh[6],  zh[7]);
        *(float4*)(zr + 8) = make_float4(zh[8], zh[9], zh[10], zh[11]);
        zr[12] = zh[12];
    } else {
        float zh[12];
        gaunt_contract_range<13, 25>(xc, yc, zh);
        float* zr = &pool[c * ZSTRIDE];
        zr[13] = zh[0];
        zr[14] = zh[1];
        zr[15] = zh[2];
        *(float4*)(zr + 16) = make_float4(zh[3], zh[4], zh[5],  zh[6]);
        *(float4*)(zr + 20) = make_float4(zh[7], zh[8], zh[9],  zh[10]);
        zr[24] = zh[11];
    }
    __syncthreads();

    // ---- coalesced copy to scratch ----
    float4* zg4 = (float4*)(ZS + (size_t)n * ZROW);
    const float4* p4 = (const float4*)pool;
    #pragma unroll
    for (int it = 0; it < 4; ++it) {                     // 896 float4 total
        int i = tid + it * 256;
        if (i < ZROW / 4) zg4[i] = p4[i];
    }
}

// ===================== K2: channel mixing =====================
// 256 threads: c = tid&127, h = tid>>7. Half h sums cc in [h*64, h*64+64).
__global__ void __launch_bounds__(256, 4)
k2_mix(float* __restrict__ out) {
    __shared__ __align__(16) float zs[ZROW];   // 14336 B

    const int tid = threadIdx.x;
    const int c = tid & 127;
    const int h = tid >> 7;
    const int n = blockIdx.x;

    // ---- stage z in: straight float4 copy (padded layout preserved) ----
    {
        const float4* zg4 = (const float4*)(ZS + (size_t)n * ZROW);
        float4* s4 = (float4*)zs;
        #pragma unroll
        for (int it = 0; it < 4; ++it) {
            int i = tid + it * 256;
            if (i < ZROW / 4) s4[i] = zg4[i];
        }
    }
    __syncthreads();

    // ---- per-l channel mixing, partial over cc-range ----
    unsigned long long a[12];
    float as = 0.0f;
    #pragma unroll
    for (int k = 0; k < 12; ++k) a[k] = 0ULL;

    const int cc0 = h * 64;
    #pragma unroll 2
    for (int ci = 0; ci < 64; ++ci) {
        const int cc = cc0 + ci;
        float4 wv = WZ4[cc * NC + c];
        float  w4 = WZ1[cc * NC + c];
        const float* zp = &zs[cc * ZSTRIDE];
        float4 q0 = *(const float4*)(zp);
        float4 q1 = *(const float4*)(zp + 4);
        float4 q2 = *(const float4*)(zp + 8);
        float4 q3 = *(const float4*)(zp + 12);
        float4 q4 = *(const float4*)(zp + 16);
        float4 q5 = *(const float4*)(zp + 20);
        float  zl = zp[24];
        ffma2(a[0],  pk2(q0.x, q0.y), pk2(wv.x, wv.y));
        ffma2(a[1],  pk2(q0.z, q0.w), pk2(wv.y, wv.y));
        ffma2(a[2],  pk2(q1.x, q1.y), pk2(wv.z, wv.z));
        ffma2(a[3],  pk2(q1.z, q1.w), pk2(wv.z, wv.z));
        ffma2(a[4],  pk2(q2.x, q2.y), pk2(wv.z, wv.w));
        ffma2(a[5],  pk2(q2.z, q2.w), pk2(wv.w, wv.w));
        ffma2(a[6],  pk2(q3.x, q3.y), pk2(wv.w, wv.w));
        ffma2(a[7],  pk2(q3.z, q3.w), pk2(wv.w, wv.w));
        ffma2(a[8],  pk2(q4.x, q4.y), pk2(w4, w4));
        ffma2(a[9],  pk2(q4.z, q4.w), pk2(w4, w4));
        ffma2(a[10], pk2(q5.x, q5.y), pk2(w4, w4));
        ffma2(a[11], pk2(q5.z, q5.w), pk2(w4, w4));
        as += zl * w4;
    }
    __syncthreads();   // both halves done reading zs

    // ---- cross-half reduction through zs (h=1 writes its partials) ----
    if (h == 1) {
        float* zr = &zs[c * ZSTRIDE];
        float lo0, hi0, lo1, hi1;
        #pragma unroll
        for (int k = 0; k < 6; ++k) {
            unpk2(a[2 * k],     lo0, hi0);
            unpk2(a[2 * k + 1], lo1, hi1);
            *(float4*)(zr + 4 * k) = make_float4(lo0, hi0, lo1, hi1);
        }
        zr[24] = as;
    }
    __syncthreads();

    float fin[DZ];
    if (h == 0) {
        const float* zr = &zs[c * ZSTRIDE];
        #pragma unroll
        for (int k = 0; k < 12; ++k) {
            float lo, hi;
            unpk2(a[k], lo, hi);
            fin[2 * k]     = lo + zr[2 * k];
            fin[2 * k + 1] = hi + zr[2 * k + 1];
        }
        fin[24] = as + zr[24];
    }
    __syncthreads();   // reads done before overwrite

    if (h == 0) {
        float* r = &zs[c * DZ];        // stride 25 (odd) -> conflict-free
        #pragma unroll
        for (int k = 0; k < DZ; ++k) r[k] = fin[k];
    }
    __syncthreads();

    // ---- fully coalesced copy to out: 3200 floats = 800 float4 ----
    float* og = out + (size_t)n * (NC * DZ);            // n*12800B: 16B aligned
    float4* og4 = (float4*)og;
    const float4* s4 = (const float4*)zs;
    #pragma unroll
    for (int it = 0; it < 4; ++it) {
        int i = tid + it * 256;
        if (i < (NC * DZ) / 4) og4[i] = s4[i];
    }
}

extern "C" void kernel_launch(void* const* d_in, const int* in_sizes, int n_in,
                              void* d_out, int out_size) {
    const float* x  = (const float*)d_in[0];
    const float* y  = (const float*)d_in[1];
    const float* wx = (const float*)d_in[2];
    const float* wy = (const float*)d_in[3];
    const float* wz = (const float*)d_in[4];
    float* out = (float*)d_out;

    pack_weights<<<64, 256>>>(wx, wy, wz);
    k1_linear_gaunt<<<NBATCH, 256>>>(x, y);
    k2_mix<<<NBATCH, 256>>>(out);
}